// round 12
// baseline (speedup 1.0000x reference)
#include <cuda_runtime.h>
#include <cuda_fp16.h>
#include <cstdint>

#define NT_MAX 1563           // ceil(100000/64)

// ---------------- device scratch (no allocs allowed) ----------------
// W1 pre-swizzled fp16 images: [kt=4][hi 32KB | lo 32KB]  (B operand [N=256][K=64] per chunk)
__device__ __align__(16) unsigned char g_W1sw[4 * 65536];
// W2 pre-swizzled fp16: [kt=2][hi 16KB | lo 16KB]  ([N=128][K=64] per chunk)
__device__ __align__(16) unsigned char g_W2sw[2 * 32768];
// h1 per-tile A images (single fp16): per 64-row tile: [ck=2][8KB] = 16KB
__device__ __align__(16) unsigned char g_h1img[(size_t)NT_MAX * 16384];

// ---------------- helpers ----------------
__device__ __forceinline__ uint32_t s2u(const void* p) {
    uint32_t a;
    asm("{ .reg .u64 t; cvta.to.shared.u64 t, %1; cvt.u32.u64 %0, t; }" : "=r"(a) : "l"(p));
    return a;
}
#define SW128(o) ((o) ^ (((o) >> 3) & 0x70))

#define LDSM4(R0, R1, R2, R3, A) \
    asm volatile("ldmatrix.sync.aligned.m8n8.x4.shared.b16 {%0,%1,%2,%3}, [%4];" \
                 : "=r"(R0), "=r"(R1), "=r"(R2), "=r"(R3) : "r"(A))

__device__ __forceinline__ void mma_f16(float d[4], const uint32_t a[4], const uint32_t b[2]) {
    asm volatile(
        "mma.sync.aligned.m16n8k16.row.col.f32.f16.f16.f32 "
        "{%0,%1,%2,%3}, {%4,%5,%6,%7}, {%8,%9}, {%0,%1,%2,%3};"
        : "+f"(d[0]), "+f"(d[1]), "+f"(d[2]), "+f"(d[3])
        : "r"(a[0]), "r"(a[1]), "r"(a[2]), "r"(a[3]), "r"(b[0]), "r"(b[1]));
}

__device__ __forceinline__ void cpa16(uint32_t saddr, const void* g) {
    asm volatile("cp.async.cg.shared.global [%0], [%1], 16;" :: "r"(saddr), "l"(g));
}
#define CP_COMMIT() asm volatile("cp.async.commit_group;" ::: "memory")
#define CP_WAIT0()  asm volatile("cp.async.wait_group 0;" ::: "memory")

__device__ __forceinline__ uint2 cvt4h(float4 v) {
    __half2 p0 = __floats2half2_rn(v.x, v.y);
    __half2 p1 = __floats2half2_rn(v.z, v.w);
    uint2 r;
    r.x = *reinterpret_cast<uint32_t*>(&p0);
    r.y = *reinterpret_cast<uint32_t*>(&p1);
    return r;
}

// h = relu( sigmoid(-uz) * tanh(uh) )   [GRU cell with h0 = 0]
__device__ __forceinline__ float gate_act(float uz, float uh) {
    float s = 1.0f / (1.0f + __expf(uz));
    float t = tanhf(uh);
    return fmaxf(s * t, 0.0f);
}

// ---------------- prep: combine W[0,0]+W[1,0], interleave z/h cols, split fp16 hi/lo, swizzle ----------------
__global__ void prep_kernel(const float* __restrict__ wz1, const float* __restrict__ wh1,
                            const float* __restrict__ wz2, const float* __restrict__ wh2) {
    int i = blockIdx.x * blockDim.x + threadIdx.x;   // 65536 threads
    {   // W1: B operand [n=256][k=256]; n=2j -> z_j, n=2j+1 -> h_j
        int nn = i >> 8, k = i & 255;
        int j = nn >> 1;
        const float* src = (nn & 1) ? wh1 : wz1;
        float w = src[k * 128 + j] + src[49152 + k * 128 + j];
        __half hb = __float2half_rn(w);
        __half lb = __float2half_rn(w - __half2float(hb));
        int kt = k >> 6, kk = k & 63;
        uint32_t o = (uint32_t)(kt * 65536) + SW128((uint32_t)(nn * 128 + kk * 2));
        *(__half*)(g_W1sw + o) = hb;
        *(__half*)(g_W1sw + o + 32768) = lb;
    }
    if (i < 16384) {   // W2: [n=128][k=128]
        int nn = i >> 7, k = i & 127;
        int j = nn >> 1;
        const float* src = (nn & 1) ? wh2 : wz2;
        float w = src[k * 64 + j] + src[12288 + k * 64 + j];
        __half hb = __float2half_rn(w);
        __half lb = __float2half_rn(w - __half2float(hb));
        int kt = k >> 6, kk = k & 63;
        uint32_t o = (uint32_t)(kt * 32768) + SW128((uint32_t)(nn * 128 + kk * 2));
        *(__half*)(g_W2sw + o) = hb;
        *(__half*)(g_W2sw + o + 16384) = lb;
    }
}

// =================== layer 1: BM=64, BN=128 (grid.y = N-half), K=256, fp16 2-term ===================
// 256 threads (8 warps, 4x2 grid of 16x64 warp tiles), 2 CTAs/SM.
// SMEM (80KB): [0] A0 8K  [8192] A1 8K  [16384] B0 32K (hi|lo)  [49152] B1 32K
// Stage (h1 half-image, 8KB) reuses B0 region after the mainloop.
#define SM1_BYTES 81920

__global__ void __launch_bounds__(256, 2)
layer1_mma(const float* __restrict__ x, const float* __restrict__ bz,
           const float* __restrict__ bh, int n) {
    extern __shared__ __align__(128) char sm[];
    const uint32_t sb = s2u(sm);
    const int tid = threadIdx.x, l = tid & 31, w = tid >> 5;
    const int wm = w >> 1, wn = w & 1;          // 4x2 warp grid, warp tile 16x64
    const int by = blockIdx.y;                  // N-half

    const int arow0 = wm * 16 + (l & 15);
    const uint32_t kba = (uint32_t)(((l >> 4) & 1) * 16);
    const int brow0 = wn * 64 + 8 * ((l >> 4) & 1) + (l & 7);
    const uint32_t kbb = (uint32_t)(((l >> 3) & 1) * 16);

    const int r0 = blockIdx.x * 64;
    const int iq = tid & 15;                    // 16 lanes cover one row's 64 K-values

    float acc[8][4];
#pragma unroll
    for (int nj = 0; nj < 8; nj++)
#pragma unroll
        for (int q = 0; q < 4; q++) acc[nj][q] = 0.0f;

    uint2 xh[4];
    // ---- prologue: x chunk0 -> fp16 regs, B chunk0 via cp.async ----
#pragma unroll
    for (int p = 0; p < 4; p++) {
        int gr = r0 + (tid >> 4) + p * 16; if (gr >= n) gr = n - 1;
        xh[p] = cvt4h(*(const float4*)(x + (size_t)gr * 256 + iq * 4));
    }
    {
        const char* sh = (const char*)g_W1sw + (size_t)by * 16384;
        const char* sl = sh + 32768;
#pragma unroll
        for (int i = 0; i < 4; i++) {
            int idx = tid + i * 256;
            cpa16(sb + 16384u + (uint32_t)idx * 16u, sh + (size_t)idx * 16);
            cpa16(sb + 32768u + (uint32_t)idx * 16u, sl + (size_t)idx * 16);
        }
        CP_COMMIT();
    }

    // =================== mainloop: 4 K-chunks, fully double-buffered, 1 sync/chunk ===================
    for (int kt = 0; kt < 4; kt++) {
        const uint32_t aB = (uint32_t)(kt & 1) * 8192u;
        const uint32_t bB = 16384u + (uint32_t)(kt & 1) * 32768u;

        // store A chunk kt (safe: all warps passed previous sync => done reading this buffer)
#pragma unroll
        for (int p = 0; p < 4; p++) {
            int row = (tid >> 4) + p * 16;
            uint32_t o = aB + SW128((uint32_t)(row * 128 + iq * 8));
            *(uint2*)(sm + o) = xh[p];
        }
        // prefetch + convert next x chunk (hidden behind this chunk's compute)
        if (kt < 3) {
#pragma unroll
            for (int p = 0; p < 4; p++) {
                int gr = r0 + (tid >> 4) + p * 16; if (gr >= n) gr = n - 1;
                xh[p] = cvt4h(*(const float4*)(x + (size_t)gr * 256 + (kt + 1) * 64 + iq * 4));
            }
        }
        CP_WAIT0();            // B chunk kt arrived
        __syncthreads();       // A stores + B visible; prior chunk's readers done

        // issue next B chunk into the other buffer (lands during this chunk's compute)
        if (kt < 3) {
            const char* sh = (const char*)g_W1sw + (size_t)(kt + 1) * 65536 + (size_t)by * 16384;
            const char* sl = sh + 32768;
            uint32_t dstB = 16384u + (uint32_t)((kt + 1) & 1) * 32768u;
#pragma unroll
            for (int i = 0; i < 4; i++) {
                int idx = tid + i * 256;
                cpa16(sb + dstB + (uint32_t)idx * 16u, sh + (size_t)idx * 16);
                cpa16(sb + dstB + 16384u + (uint32_t)idx * 16u, sl + (size_t)idx * 16);
            }
            CP_COMMIT();
        }

        // ---- compute: 2-term (A·Bh, A·Bl) ----
#pragma unroll
        for (int kk = 0; kk < 4; kk++) {
            uint32_t af[4], bfr[8][2];
            {
                int row = arow0;
                uint32_t off = (uint32_t)(row * 128) + (((uint32_t)(kk * 32) + kba) ^ (uint32_t)((row & 7) << 4));
                LDSM4(af[0], af[1], af[2], af[3], sb + aB + off);
            }
#pragma unroll
            for (int g = 0; g < 4; g++) {
                int row = brow0 + g * 16;
                uint32_t off = (uint32_t)(row * 128) + (((uint32_t)(kk * 32) + kbb) ^ (uint32_t)((row & 7) << 4));
                LDSM4(bfr[2 * g][0], bfr[2 * g][1], bfr[2 * g + 1][0], bfr[2 * g + 1][1], sb + bB + off);
            }
#pragma unroll
            for (int nj = 0; nj < 8; nj++) mma_f16(acc[nj], af, bfr[nj]);
#pragma unroll
            for (int g = 0; g < 4; g++) {
                int row = brow0 + g * 16;
                uint32_t off = (uint32_t)(row * 128) + (((uint32_t)(kk * 32) + kbb) ^ (uint32_t)((row & 7) << 4));
                LDSM4(bfr[2 * g][0], bfr[2 * g][1], bfr[2 * g + 1][0], bfr[2 * g + 1][1], sb + bB + 16384u + off);
            }
#pragma unroll
            for (int nj = 0; nj < 8; nj++) mma_f16(acc[nj], af, bfr[nj]);
        }
    }

    // ---- epilogue: act, single fp16, stage h1 half-image (ck = by) in B0 region ----
    // Stage [16384, 24576) is disjoint from kt=3's live buffers (A1, B1) => no sync needed first.
#pragma unroll
    for (int nj = 0; nj < 8; nj++) {
        int rlo = wm * 16 + (l >> 2);
        int j = by * 64 + wn * 32 + nj * 4 + (l & 3);       // global h1 column (pair idx)
        float v0 = gate_act(acc[nj][0] + __ldg(bz + j), acc[nj][1] + __ldg(bh + j));
        float v1 = gate_act(acc[nj][2] + __ldg(bz + j), acc[nj][3] + __ldg(bh + j));
        int kk2 = j & 63;
        uint32_t o0 = 16384u + SW128((uint32_t)(rlo * 128 + kk2 * 2));
        uint32_t o1 = 16384u + SW128((uint32_t)((rlo + 8) * 128 + kk2 * 2));
        *(__half*)(sm + o0) = __float2half_rn(v0);
        *(__half*)(sm + o1) = __float2half_rn(v1);
    }
    __syncthreads();
    {   // stage (8KB) -> g_h1img tile section ck=by, coalesced
        const uint4* s4 = (const uint4*)(sm + 16384);
        uint4* d4 = (uint4*)(g_h1img + (size_t)blockIdx.x * 16384 + (size_t)by * 8192);
#pragma unroll
        for (int i = 0; i < 2; i++) d4[tid + i * 256] = s4[tid + i * 256];
    }
}

// =================== layer 2 + lin1 + lin2: BM=64, BN=128, K=128 (2 chunks), fp16 2-term ===================
// SMEM: [0] A0 8K [8192] A1 8K [16384] B0 32K [49152] B1 32K
//       [81920] w3s 4K [86016] b3s 64B [86080] w4s 64B [86144] bzs 256B [86400] bhs 256B
// h2s (64*65*4 = 16640B) overlaps [0, 16640) after the mainloop.
#define SM2_BYTES 86656

__global__ void __launch_bounds__(256, 2)
layer2_mma(const float* __restrict__ bz, const float* __restrict__ bh,
           const float* __restrict__ w3, const float* __restrict__ b3,
           const float* __restrict__ w4, const float* __restrict__ b4,
           float* __restrict__ out, int n) {
    extern __shared__ __align__(128) char sm[];
    const uint32_t sb = s2u(sm);
    const int tid = threadIdx.x, l = tid & 31, w = tid >> 5;
    const int wm = w >> 1, wn = w & 1;          // 4x2 warp grid, warp tile 16x64
    float* w3s = (float*)(sm + 81920);
    float* b3s = (float*)(sm + 86016);
    float* w4s = (float*)(sm + 86080);
    float* bzs = (float*)(sm + 86144);
    float* bhs = (float*)(sm + 86400);
#pragma unroll
    for (int i = 0; i < 4; i++) w3s[tid + i * 256] = w3[tid + i * 256];
    if (tid < 16) { b3s[tid] = b3[tid]; w4s[tid] = w4[tid]; }
    if (tid < 64) { bzs[tid] = bz[tid]; bhs[tid] = bh[tid]; }

    float acc[8][4];
#pragma unroll
    for (int nj = 0; nj < 8; nj++)
#pragma unroll
        for (int q = 0; q < 4; q++) acc[nj][q] = 0.0f;

    const int arow0 = wm * 16 + (l & 15);
    const uint32_t kba = (uint32_t)(((l >> 4) & 1) * 16);
    const int brow0 = wn * 64 + 8 * ((l >> 4) & 1) + (l & 7);
    const uint32_t kbb = (uint32_t)(((l >> 3) & 1) * 16);

    const int r0 = blockIdx.x * 64;

    // ---- prologue: A0 (8K) + B0 (32K) via cp.async ----
    {
        const char* gA = (const char*)g_h1img + (size_t)blockIdx.x * 16384;
        const char* gB = (const char*)g_W2sw;
#pragma unroll
        for (int i = 0; i < 2; i++) {
            int idx = tid + i * 256;
            cpa16(sb + (uint32_t)idx * 16u, gA + (size_t)idx * 16);
        }
#pragma unroll
        for (int i = 0; i < 8; i++) {
            int idx = tid + i * 256;
            cpa16(sb + 16384u + (uint32_t)idx * 16u, gB + (size_t)idx * 16);
        }
        CP_COMMIT();
    }

    for (int kt = 0; kt < 2; kt++) {
        const uint32_t aB = (uint32_t)kt * 8192u;
        const uint32_t bB = 16384u + (uint32_t)kt * 32768u;

        CP_WAIT0();
        __syncthreads();

        if (kt == 0) {   // prefetch chunk 1 during chunk 0 compute
            const char* gA = (const char*)g_h1img + (size_t)blockIdx.x * 16384 + 8192;
            const char* gB = (const char*)g_W2sw + 32768;
#pragma unroll
            for (int i = 0; i < 2; i++) {
                int idx = tid + i * 256;
                cpa16(sb + 8192u + (uint32_t)idx * 16u, gA + (size_t)idx * 16);
            }
#pragma unroll
            for (int i = 0; i < 8; i++) {
                int idx = tid + i * 256;
                cpa16(sb + 49152u + (uint32_t)idx * 16u, gB + (size_t)idx * 16);
            }
            CP_COMMIT();
        }

        // ---- compute: 2-term (A·Bh, A·Bl) ----
#pragma unroll
        for (int kk = 0; kk < 4; kk++) {
            uint32_t af[4], bfr[8][2];
            {
                int row = arow0;
                uint32_t off = (uint32_t)(row * 128) + (((uint32_t)(kk * 32) + kba) ^ (uint32_t)((row & 7) << 4));
                LDSM4(af[0], af[1], af[2], af[3], sb + aB + off);
            }
#pragma unroll
            for (int g = 0; g < 4; g++) {
                int row = brow0 + g * 16;
                uint32_t off = (uint32_t)(row * 128) + (((uint32_t)(kk * 32) + kbb) ^ (uint32_t)((row & 7) << 4));
                LDSM4(bfr[2 * g][0], bfr[2 * g][1], bfr[2 * g + 1][0], bfr[2 * g + 1][1], sb + bB + off);
            }
#pragma unroll
            for (int nj = 0; nj < 8; nj++) mma_f16(acc[nj], af, bfr[nj]);
#pragma unroll
            for (int g = 0; g < 4; g++) {
                int row = brow0 + g * 16;
                uint32_t off = (uint32_t)(row * 128) + (((uint32_t)(kk * 32) + kbb) ^ (uint32_t)((row & 7) << 4));
                LDSM4(bfr[2 * g][0], bfr[2 * g][1], bfr[2 * g + 1][0], bfr[2 * g + 1][1], sb + bB + 16384u + off);
            }
#pragma unroll
            for (int nj = 0; nj < 8; nj++) mma_f16(acc[nj], af, bfr[nj]);
        }
    }
    __syncthreads();   // all compute done before h2s overwrites A/B regions

    // ---- epilogue: h2 -> smem ----
    float* h2s = (float*)sm;    // [64][65]
#pragma unroll
    for (int nj = 0; nj < 8; nj++) {
        int rlo = wm * 16 + (l >> 2);
        int j = wn * 32 + nj * 4 + (l & 3);
        float v0 = gate_act(acc[nj][0] + bzs[j], acc[nj][1] + bhs[j]);
        float v1 = gate_act(acc[nj][2] + bzs[j], acc[nj][3] + bhs[j]);
        h2s[rlo * 65 + j] = v0;
        h2s[(rlo + 8) * 65 + j] = v1;
    }
    __syncthreads();

    // ---- lin1(relu) + lin2: one thread per row ----
    if (tid < 64) {
        float s[16];
#pragma unroll
        for (int u = 0; u < 16; u++) s[u] = b3s[u];
#pragma unroll 4
        for (int j = 0; j < 64; j++) {
            float v = h2s[tid * 65 + j];
#pragma unroll
            for (int u = 0; u < 16; u++) s[u] = fmaf(v, w3s[j * 16 + u], s[u]);
        }
        float o2 = __ldg(b4);
#pragma unroll
        for (int u = 0; u < 16; u++) o2 += fmaxf(s[u], 0.0f) * w4s[u];
        int gr = r0 + tid;
        if (gr < n) out[gr] = o2;
    }
}

extern "C" void kernel_launch(void* const* d_in, const int* in_sizes, int n_in,
                              void* d_out, int out_size) {
    const float* x   = (const float*)d_in[0];
    const float* wz1 = (const float*)d_in[3];
    const float* bz1 = (const float*)d_in[4];
    const float* wh1 = (const float*)d_in[7];
    const float* bh1 = (const float*)d_in[8];
    const float* wz2 = (const float*)d_in[9];
    const float* bz2 = (const float*)d_in[10];
    const float* wh2 = (const float*)d_in[13];
    const float* bh2 = (const float*)d_in[14];
    const float* w3  = (const float*)d_in[15];
    const float* b3  = (const float*)d_in[16];
    const float* w4  = (const float*)d_in[17];
    const float* b4  = (const float*)d_in[18];

    const int n  = in_sizes[0] / 256;          // 100000
    const int nt = (n + 63) / 64;              // 1563

    cudaFuncSetAttribute(layer1_mma, cudaFuncAttributeMaxDynamicSharedMemorySize, SM1_BYTES);
    cudaFuncSetAttribute(layer2_mma, cudaFuncAttributeMaxDynamicSharedMemorySize, SM2_BYTES);

    prep_kernel<<<256, 256>>>(wz1, wh1, wz2, wh2);
    layer1_mma<<<dim3(nt, 2), 256, SM1_BYTES>>>(x, bz1, bh1, n);
    layer2_mma<<<nt, 256, SM2_BYTES>>>(bz2, bh2, w3, b3, w4, b4, (float*)d_out, n);
}

// round 13
// speedup vs baseline: 1.1525x; 1.1525x over previous
#include <cuda_runtime.h>
#include <cuda_fp16.h>
#include <cstdint>

#define NB_MAX 782            // ceil(100000/128)

// ---------------- device scratch (no allocs allowed) ----------------
// W1 pre-swizzled fp16 images: [kt=4][hi 32KB | lo 32KB]  (B operand [N=256][K=64] per chunk)
__device__ __align__(16) unsigned char g_W1sw[4 * 65536];
// W2 pre-swizzled fp16: [kt=2][hi 16KB | lo 16KB]  ([N=128][K=64] per chunk)
__device__ __align__(16) unsigned char g_W2sw[2 * 32768];
// h1 per-tile A images (single fp16): [ck=2][16KB] = 32KB per 128-row tile
__device__ __align__(16) unsigned char g_h1img[(size_t)NB_MAX * 32768];

// ---------------- helpers ----------------
__device__ __forceinline__ uint32_t s2u(const void* p) {
    uint32_t a;
    asm("{ .reg .u64 t; cvta.to.shared.u64 t, %1; cvt.u32.u64 %0, t; }" : "=r"(a) : "l"(p));
    return a;
}
#define SW128(o) ((o) ^ (((o) >> 3) & 0x70))

#define LDSM4(R0, R1, R2, R3, A) \
    asm volatile("ldmatrix.sync.aligned.m8n8.x4.shared.b16 {%0,%1,%2,%3}, [%4];" \
                 : "=r"(R0), "=r"(R1), "=r"(R2), "=r"(R3) : "r"(A))

__device__ __forceinline__ void mma_f16(float d[4], const uint32_t a[4], const uint32_t b[2]) {
    asm volatile(
        "mma.sync.aligned.m16n8k16.row.col.f32.f16.f16.f32 "
        "{%0,%1,%2,%3}, {%4,%5,%6,%7}, {%8,%9}, {%0,%1,%2,%3};"
        : "+f"(d[0]), "+f"(d[1]), "+f"(d[2]), "+f"(d[3])
        : "r"(a[0]), "r"(a[1]), "r"(a[2]), "r"(a[3]), "r"(b[0]), "r"(b[1]));
}

__device__ __forceinline__ void cpa16(uint32_t saddr, const void* g) {
    asm volatile("cp.async.cg.shared.global [%0], [%1], 16;" :: "r"(saddr), "l"(g));
}
#define CP_COMMIT() asm volatile("cp.async.commit_group;" ::: "memory")
#define CP_WAIT0()  asm volatile("cp.async.wait_group 0;" ::: "memory")

__device__ __forceinline__ uint2 cvt4h(float4 v) {
    __half2 p0 = __floats2half2_rn(v.x, v.y);
    __half2 p1 = __floats2half2_rn(v.z, v.w);
    uint2 r;
    r.x = *reinterpret_cast<uint32_t*>(&p0);
    r.y = *reinterpret_cast<uint32_t*>(&p1);
    return r;
}

// h = relu( sigmoid(-uz) * tanh(uh) )   [GRU cell with h0 = 0]
__device__ __forceinline__ float gate_act(float uz, float uh) {
    float s = 1.0f / (1.0f + __expf(uz));
    float t = tanhf(uh);
    return fmaxf(s * t, 0.0f);
}

// ---------------- prep: combine W[0,0]+W[1,0], interleave z/h cols, split fp16 hi/lo, swizzle ----------------
__global__ void prep_kernel(const float* __restrict__ wz1, const float* __restrict__ wh1,
                            const float* __restrict__ wz2, const float* __restrict__ wh2) {
    int i = blockIdx.x * blockDim.x + threadIdx.x;   // 65536 threads
    {   // W1: B operand [n=256][k=256]; n=2j -> z_j, n=2j+1 -> h_j
        int nn = i >> 8, k = i & 255;
        int j = nn >> 1;
        const float* src = (nn & 1) ? wh1 : wz1;
        float w = src[k * 128 + j] + src[49152 + k * 128 + j];
        __half hb = __float2half_rn(w);
        __half lb = __float2half_rn(w - __half2float(hb));
        int kt = k >> 6, kk = k & 63;
        uint32_t o = (uint32_t)(kt * 65536) + SW128((uint32_t)(nn * 128 + kk * 2));
        *(__half*)(g_W1sw + o) = hb;
        *(__half*)(g_W1sw + o + 32768) = lb;
    }
    if (i < 16384) {   // W2: [n=128][k=128], single fp16 (layer2 runs 1-term)
        int nn = i >> 7, k = i & 127;
        int j = nn >> 1;
        const float* src = (nn & 1) ? wh2 : wz2;
        float w = src[k * 64 + j] + src[12288 + k * 64 + j];
        __half hb = __float2half_rn(w);
        int kt = k >> 6, kk = k & 63;
        uint32_t o = (uint32_t)(kt * 32768) + SW128((uint32_t)(nn * 128 + kk * 2));
        *(__half*)(g_W2sw + o) = hb;
    }
}

// =================== layer 1: BM=128, BN=128 (grid.y = N-half), K=256, fp16 2-term ===================
// 256 threads, 2 CTAs/SM.  SMEM (96KB):
//   [0     ] A0 16K   [16384] A1 16K       (x chunk, single fp16)
//   [32768 ] B0 32K (hi 16K | lo 16K)  [65536] B1 32K
// Stage (h1 half-image, 16KB) reuses B0 region after the mainloop.
#define SM1_BYTES 98304

__global__ void __launch_bounds__(256, 2)
layer1_mma(const float* __restrict__ x, const float* __restrict__ bz,
           const float* __restrict__ bh, int n) {
    extern __shared__ __align__(128) char sm[];
    const uint32_t sb = s2u(sm);
    const int tid = threadIdx.x, l = tid & 31, w = tid >> 5;
    const int wm = w >> 1, wn = w & 1;          // 4x2 warp grid, warp tile 32x64
    const int by = blockIdx.y;                  // N-half

    const int arow0 = wm * 32 + (l & 15);
    const uint32_t kba = (uint32_t)(((l >> 4) & 1) * 16);
    const int brow0 = wn * 64 + 8 * ((l >> 4) & 1) + (l & 7);
    const uint32_t kbb = (uint32_t)(((l >> 3) & 1) * 16);

    const int r0 = blockIdx.x * 128;
    const int iq = tid & 15;                    // 16 lanes cover one row's 64 K-values

    float acc[2][8][4];
#pragma unroll
    for (int mi = 0; mi < 2; mi++)
#pragma unroll
        for (int nj = 0; nj < 8; nj++)
#pragma unroll
            for (int q = 0; q < 4; q++) acc[mi][nj][q] = 0.0f;

    uint2 xh[8];
    // ---- prologue: x chunk0 -> fp16 regs, B chunk0 via cp.async ----
#pragma unroll
    for (int p = 0; p < 8; p++) {
        int gr = r0 + (tid >> 4) + p * 16; if (gr >= n) gr = n - 1;
        xh[p] = cvt4h(*(const float4*)(x + (size_t)gr * 256 + iq * 4));
    }
    {
        const char* sh = (const char*)g_W1sw + (size_t)by * 16384;
        const char* sl = sh + 32768;
#pragma unroll
        for (int i = 0; i < 4; i++) {
            int idx = tid + i * 256;
            cpa16(sb + 32768u + (uint32_t)idx * 16u, sh + (size_t)idx * 16);
            cpa16(sb + 49152u + (uint32_t)idx * 16u, sl + (size_t)idx * 16);
        }
        CP_COMMIT();
    }

    // =================== mainloop: 4 K-chunks, fully double-buffered, 1 sync/chunk ===================
    for (int kt = 0; kt < 4; kt++) {
        const uint32_t aB = (uint32_t)(kt & 1) * 16384u;
        const uint32_t bB = 32768u + (uint32_t)(kt & 1) * 32768u;

        // store A chunk kt (safe: all warps passed previous sync => done reading this buffer)
#pragma unroll
        for (int p = 0; p < 8; p++) {
            int row = (tid >> 4) + p * 16;
            uint32_t o = aB + SW128((uint32_t)(row * 128 + iq * 8));
            *(uint2*)(sm + o) = xh[p];
        }
        // prefetch + convert next x chunk (hidden behind this chunk's compute)
        if (kt < 3) {
#pragma unroll
            for (int p = 0; p < 8; p++) {
                int gr = r0 + (tid >> 4) + p * 16; if (gr >= n) gr = n - 1;
                xh[p] = cvt4h(*(const float4*)(x + (size_t)gr * 256 + (kt + 1) * 64 + iq * 4));
            }
        }
        CP_WAIT0();            // B chunk kt arrived
        __syncthreads();       // A stores + B visible; prior chunk's readers done

        // issue next B chunk into the other buffer (lands during this chunk's compute)
        if (kt < 3) {
            const char* sh = (const char*)g_W1sw + (size_t)(kt + 1) * 65536 + (size_t)by * 16384;
            const char* sl = sh + 32768;
            uint32_t dstB = 32768u + (uint32_t)((kt + 1) & 1) * 32768u;
#pragma unroll
            for (int i = 0; i < 4; i++) {
                int idx = tid + i * 256;
                cpa16(sb + dstB + (uint32_t)idx * 16u, sh + (size_t)idx * 16);
                cpa16(sb + dstB + 16384u + (uint32_t)idx * 16u, sl + (size_t)idx * 16);
            }
            CP_COMMIT();
        }

        // ---- compute: 2-term (A·Bh, A·Bl) ----
#pragma unroll
        for (int kk = 0; kk < 4; kk++) {
            uint32_t af[2][4], bfr[8][2];
#pragma unroll
            for (int mi = 0; mi < 2; mi++) {
                int row = arow0 + mi * 16;
                uint32_t off = (uint32_t)(row * 128) + (((uint32_t)(kk * 32) + kba) ^ (uint32_t)((row & 7) << 4));
                LDSM4(af[mi][0], af[mi][1], af[mi][2], af[mi][3], sb + aB + off);
            }
#pragma unroll
            for (int g = 0; g < 4; g++) {
                int row = brow0 + g * 16;
                uint32_t off = (uint32_t)(row * 128) + (((uint32_t)(kk * 32) + kbb) ^ (uint32_t)((row & 7) << 4));
                LDSM4(bfr[2 * g][0], bfr[2 * g][1], bfr[2 * g + 1][0], bfr[2 * g + 1][1], sb + bB + off);
            }
#pragma unroll
            for (int mi = 0; mi < 2; mi++)
#pragma unroll
                for (int nj = 0; nj < 8; nj++) mma_f16(acc[mi][nj], af[mi], bfr[nj]);
#pragma unroll
            for (int g = 0; g < 4; g++) {
                int row = brow0 + g * 16;
                uint32_t off = (uint32_t)(row * 128) + (((uint32_t)(kk * 32) + kbb) ^ (uint32_t)((row & 7) << 4));
                LDSM4(bfr[2 * g][0], bfr[2 * g][1], bfr[2 * g + 1][0], bfr[2 * g + 1][1], sb + bB + 16384u + off);
            }
#pragma unroll
            for (int mi = 0; mi < 2; mi++)
#pragma unroll
                for (int nj = 0; nj < 8; nj++) mma_f16(acc[mi][nj], af[mi], bfr[nj]);
        }
    }

    // ---- epilogue: act, single fp16, stage h1 half-image (ck = by) in B0 region ----
    // Stage [32768, 49152) is disjoint from kt=3's live buffers (A1, B1) => no sync needed first.
#pragma unroll
    for (int mi = 0; mi < 2; mi++)
#pragma unroll
        for (int nj = 0; nj < 8; nj++) {
            int rlo = wm * 32 + mi * 16 + (l >> 2);
            int j = by * 64 + wn * 32 + nj * 4 + (l & 3);       // global h1 column
            float v0 = gate_act(acc[mi][nj][0] + __ldg(bz + j), acc[mi][nj][1] + __ldg(bh + j));
            float v1 = gate_act(acc[mi][nj][2] + __ldg(bz + j), acc[mi][nj][3] + __ldg(bh + j));
            int kk2 = j & 63;
            uint32_t o0 = 32768u + SW128((uint32_t)(rlo * 128 + kk2 * 2));
            uint32_t o1 = 32768u + SW128((uint32_t)((rlo + 8) * 128 + kk2 * 2));
            *(__half*)(sm + o0) = __float2half_rn(v0);
            *(__half*)(sm + o1) = __float2half_rn(v1);
        }
    __syncthreads();
    {   // stage (16KB) -> g_h1img tile section ck=by, coalesced
        const uint4* s4 = (const uint4*)(sm + 32768);
        uint4* d4 = (uint4*)(g_h1img + (size_t)blockIdx.x * 32768 + (size_t)by * 16384);
#pragma unroll
        for (int i = 0; i < 4; i++) d4[tid + i * 256] = s4[tid + i * 256];
    }
}

// =================== layer 2 + lin1 + lin2: BM=128, BN=128, K=128 (2 chunks), fp16 1-term ===================
// SMEM: [0] A0 16K [16384] A1 16K [32768] B0 16K [49152] B1 16K
//       [65536] w3s 4K [69632] b3s 64B [69696] w4s 64B [69760] bzs 256B [70016] bhs 256B  total 70272
// h2s (128*65*4 = 33280B) overlaps [0, 33280) after the mainloop.
#define SM2_BYTES 70272

__global__ void __launch_bounds__(256, 2)
layer2_mma(const float* __restrict__ bz, const float* __restrict__ bh,
           const float* __restrict__ w3, const float* __restrict__ b3,
           const float* __restrict__ w4, const float* __restrict__ b4,
           float* __restrict__ out, int n) {
    extern __shared__ __align__(128) char sm[];
    const uint32_t sb = s2u(sm);
    const int tid = threadIdx.x, l = tid & 31, w = tid >> 5;
    const int wm = w >> 1, wn = w & 1;          // 4x2 warp grid, warp tile 32x64
    float* w3s = (float*)(sm + 65536);
    float* b3s = (float*)(sm + 69632);
    float* w4s = (float*)(sm + 69696);
    float* bzs = (float*)(sm + 69760);
    float* bhs = (float*)(sm + 70016);
#pragma unroll
    for (int i = 0; i < 4; i++) w3s[tid + i * 256] = w3[tid + i * 256];
    if (tid < 16) { b3s[tid] = b3[tid]; w4s[tid] = w4[tid]; }
    if (tid < 64) { bzs[tid] = bz[tid]; bhs[tid] = bh[tid]; }

    float acc[2][8][4];
#pragma unroll
    for (int mi = 0; mi < 2; mi++)
#pragma unroll
        for (int nj = 0; nj < 8; nj++)
#pragma unroll
            for (int q = 0; q < 4; q++) acc[mi][nj][q] = 0.0f;

    const int arow0 = wm * 32 + (l & 15);
    const uint32_t kba = (uint32_t)(((l >> 4) & 1) * 16);
    const int brow0 = wn * 64 + 8 * ((l >> 4) & 1) + (l & 7);
    const uint32_t kbb = (uint32_t)(((l >> 3) & 1) * 16);

    const int r0 = blockIdx.x * 128;

    // ---- prologue: A0 (16K) + B0-hi (16K) via cp.async ----
    {
        const char* gA = (const char*)g_h1img + (size_t)blockIdx.x * 32768;
        const char* gB = (const char*)g_W2sw;
#pragma unroll
        for (int i = 0; i < 4; i++) {
            int idx = tid + i * 256;
            cpa16(sb + (uint32_t)idx * 16u, gA + (size_t)idx * 16);
            cpa16(sb + 32768u + (uint32_t)idx * 16u, gB + (size_t)idx * 16);
        }
        CP_COMMIT();
    }

    for (int kt = 0; kt < 2; kt++) {
        const uint32_t aB = (uint32_t)kt * 16384u;
        const uint32_t bB = 32768u + (uint32_t)kt * 16384u;

        CP_WAIT0();
        __syncthreads();

        if (kt == 0) {   // prefetch chunk 1 during chunk 0 compute
            const char* gA = (const char*)g_h1img + (size_t)blockIdx.x * 32768 + 16384;
            const char* gB = (const char*)g_W2sw + 32768;
#pragma unroll
            for (int i = 0; i < 4; i++) {
                int idx = tid + i * 256;
                cpa16(sb + 16384u + (uint32_t)idx * 16u, gA + (size_t)idx * 16);
                cpa16(sb + 49152u + (uint32_t)idx * 16u, gB + (size_t)idx * 16);
            }
            CP_COMMIT();
        }

        // ---- compute: 1-term (A·Bh) ----
#pragma unroll
        for (int kk = 0; kk < 4; kk++) {
            uint32_t af[2][4], bfr[8][2];
#pragma unroll
            for (int mi = 0; mi < 2; mi++) {
                int row = arow0 + mi * 16;
                uint32_t off = (uint32_t)(row * 128) + (((uint32_t)(kk * 32) + kba) ^ (uint32_t)((row & 7) << 4));
                LDSM4(af[mi][0], af[mi][1], af[mi][2], af[mi][3], sb + aB + off);
            }
#pragma unroll
            for (int g = 0; g < 4; g++) {
                int row = brow0 + g * 16;
                uint32_t off = (uint32_t)(row * 128) + (((uint32_t)(kk * 32) + kbb) ^ (uint32_t)((row & 7) << 4));
                LDSM4(bfr[2 * g][0], bfr[2 * g][1], bfr[2 * g + 1][0], bfr[2 * g + 1][1], sb + bB + off);
            }
#pragma unroll
            for (int mi = 0; mi < 2; mi++)
#pragma unroll
                for (int nj = 0; nj < 8; nj++) mma_f16(acc[mi][nj], af[mi], bfr[nj]);
        }
    }
    __syncthreads();   // all compute done before h2s overwrites A/B regions

    // ---- epilogue: h2 -> smem ----
    float* h2s = (float*)sm;    // [128][65]
#pragma unroll
    for (int mi = 0; mi < 2; mi++)
#pragma unroll
        for (int nj = 0; nj < 8; nj++) {
            int rlo = wm * 32 + mi * 16 + (l >> 2);
            int j = wn * 32 + nj * 4 + (l & 3);
            float v0 = gate_act(acc[mi][nj][0] + bzs[j], acc[mi][nj][1] + bhs[j]);
            float v1 = gate_act(acc[mi][nj][2] + bzs[j], acc[mi][nj][3] + bhs[j]);
            h2s[rlo * 65 + j] = v0;
            h2s[(rlo + 8) * 65 + j] = v1;
        }
    __syncthreads();

    // ---- lin1(relu) + lin2: one thread per row ----
    if (tid < 128) {
        float s[16];
#pragma unroll
        for (int u = 0; u < 16; u++) s[u] = b3s[u];
#pragma unroll 4
        for (int j = 0; j < 64; j++) {
            float v = h2s[tid * 65 + j];
#pragma unroll
            for (int u = 0; u < 16; u++) s[u] = fmaf(v, w3s[j * 16 + u], s[u]);
        }
        float o2 = __ldg(b4);
#pragma unroll
        for (int u = 0; u < 16; u++) o2 += fmaxf(s[u], 0.0f) * w4s[u];
        int gr = r0 + tid;
        if (gr < n) out[gr] = o2;
    }
}

extern "C" void kernel_launch(void* const* d_in, const int* in_sizes, int n_in,
                              void* d_out, int out_size) {
    const float* x   = (const float*)d_in[0];
    const float* wz1 = (const float*)d_in[3];
    const float* bz1 = (const float*)d_in[4];
    const float* wh1 = (const float*)d_in[7];
    const float* bh1 = (const float*)d_in[8];
    const float* wz2 = (const float*)d_in[9];
    const float* bz2 = (const float*)d_in[10];
    const float* wh2 = (const float*)d_in[13];
    const float* bh2 = (const float*)d_in[14];
    const float* w3  = (const float*)d_in[15];
    const float* b3  = (const float*)d_in[16];
    const float* w4  = (const float*)d_in[17];
    const float* b4  = (const float*)d_in[18];

    const int n  = in_sizes[0] / 256;          // 100000
    const int nb = (n + 127) / 128;            // 782

    cudaFuncSetAttribute(layer1_mma, cudaFuncAttributeMaxDynamicSharedMemorySize, SM1_BYTES);
    cudaFuncSetAttribute(layer2_mma, cudaFuncAttributeMaxDynamicSharedMemorySize, SM2_BYTES);

    prep_kernel<<<256, 256>>>(wz1, wh1, wz2, wh2);
    layer1_mma<<<dim3(nb, 2), 256, SM1_BYTES>>>(x, bz1, bh1, n);
    layer2_mma<<<nb, 256, SM2_BYTES>>>(bz2, bh2, w3, b3, w4, b4, (float*)d_out, n);
}

// round 14
// speedup vs baseline: 1.3413x; 1.1638x over previous
#include <cuda_runtime.h>
#include <cuda_fp16.h>
#include <cstdint>

#define NB_MAX 782            // ceil(100000/128)

// ---------------- device scratch (no allocs allowed) ----------------
// W1 pre-swizzled fp16 (single term): [kt=4][N=256 rows][128B] = 32KB per kt
__device__ __align__(16) unsigned char g_W1sw[4 * 32768];
// W2 pre-swizzled fp16 (single term): [kt=2][16KB]
__device__ __align__(16) unsigned char g_W2sw[2 * 16384];
// h1 per-tile A images (single fp16): [ck=2][16KB] = 32KB per 128-row tile
__device__ __align__(16) unsigned char g_h1img[(size_t)NB_MAX * 32768];

// ---------------- helpers ----------------
__device__ __forceinline__ uint32_t s2u(const void* p) {
    uint32_t a;
    asm("{ .reg .u64 t; cvta.to.shared.u64 t, %1; cvt.u32.u64 %0, t; }" : "=r"(a) : "l"(p));
    return a;
}
#define SW128(o) ((o) ^ (((o) >> 3) & 0x70))

#define LDSM4(R0, R1, R2, R3, A) \
    asm volatile("ldmatrix.sync.aligned.m8n8.x4.shared.b16 {%0,%1,%2,%3}, [%4];" \
                 : "=r"(R0), "=r"(R1), "=r"(R2), "=r"(R3) : "r"(A))

__device__ __forceinline__ void mma_f16(float d[4], const uint32_t a[4], const uint32_t b[2]) {
    asm volatile(
        "mma.sync.aligned.m16n8k16.row.col.f32.f16.f16.f32 "
        "{%0,%1,%2,%3}, {%4,%5,%6,%7}, {%8,%9}, {%0,%1,%2,%3};"
        : "+f"(d[0]), "+f"(d[1]), "+f"(d[2]), "+f"(d[3])
        : "r"(a[0]), "r"(a[1]), "r"(a[2]), "r"(a[3]), "r"(b[0]), "r"(b[1]));
}

__device__ __forceinline__ void cpa16(uint32_t saddr, const void* g) {
    asm volatile("cp.async.cg.shared.global [%0], [%1], 16;" :: "r"(saddr), "l"(g));
}
#define CP_COMMIT() asm volatile("cp.async.commit_group;" ::: "memory")
#define CP_WAIT0()  asm volatile("cp.async.wait_group 0;" ::: "memory")

__device__ __forceinline__ uint2 cvt4h(float4 v) {
    __half2 p0 = __floats2half2_rn(v.x, v.y);
    __half2 p1 = __floats2half2_rn(v.z, v.w);
    uint2 r;
    r.x = *reinterpret_cast<uint32_t*>(&p0);
    r.y = *reinterpret_cast<uint32_t*>(&p1);
    return r;
}

// h = relu( sigmoid(-uz) * tanh(uh) )   [GRU cell with h0 = 0]
__device__ __forceinline__ float gate_act(float uz, float uh) {
    float s = 1.0f / (1.0f + __expf(uz));
    float t = tanhf(uh);
    return fmaxf(s * t, 0.0f);
}

// ---------------- prep: combine W[0,0]+W[1,0], interleave z/h cols, single fp16, swizzle ----------------
__global__ void prep_kernel(const float* __restrict__ wz1, const float* __restrict__ wh1,
                            const float* __restrict__ wz2, const float* __restrict__ wh2) {
    int i = blockIdx.x * blockDim.x + threadIdx.x;   // 65536 threads
    {   // W1: B operand [n=256][k=256]; n=2j -> z_j, n=2j+1 -> h_j
        int nn = i >> 8, k = i & 255;
        int j = nn >> 1;
        const float* src = (nn & 1) ? wh1 : wz1;
        float w = src[k * 128 + j] + src[49152 + k * 128 + j];
        int kt = k >> 6, kk = k & 63;
        uint32_t o = (uint32_t)(kt * 32768) + SW128((uint32_t)(nn * 128 + kk * 2));
        *(__half*)(g_W1sw + o) = __float2half_rn(w);
    }
    if (i < 16384) {   // W2: [n=128][k=128], single fp16
        int nn = i >> 7, k = i & 127;
        int j = nn >> 1;
        const float* src = (nn & 1) ? wh2 : wz2;
        float w = src[k * 64 + j] + src[12288 + k * 64 + j];
        int kt = k >> 6, kk = k & 63;
        uint32_t o = (uint32_t)(kt * 16384) + SW128((uint32_t)(nn * 128 + kk * 2));
        *(__half*)(g_W2sw + o) = __float2half_rn(w);
    }
}

// =================== layer 1: BM=128, BN=128 (grid.y = N-half), K=256, fp16 1-term ===================
// 256 threads, 2 CTAs/SM.  SMEM (64KB):
//   [0] A0 16K  [16384] A1 16K  [32768] B0 16K  [49152] B1 16K
// Stage (h1 half-image, 16KB) reuses B0 region after the mainloop.
#define SM1_BYTES 65536

__global__ void __launch_bounds__(256, 2)
layer1_mma(const float* __restrict__ x, const float* __restrict__ bz,
           const float* __restrict__ bh, int n) {
    extern __shared__ __align__(128) char sm[];
    const uint32_t sb = s2u(sm);
    const int tid = threadIdx.x, l = tid & 31, w = tid >> 5;
    const int wm = w >> 1, wn = w & 1;          // 4x2 warp grid, warp tile 32x64
    const int by = blockIdx.y;                  // N-half

    const int arow0 = wm * 32 + (l & 15);
    const uint32_t kba = (uint32_t)(((l >> 4) & 1) * 16);
    const int brow0 = wn * 64 + 8 * ((l >> 4) & 1) + (l & 7);
    const uint32_t kbb = (uint32_t)(((l >> 3) & 1) * 16);

    const int r0 = blockIdx.x * 128;
    const int iq = tid & 15;                    // 16 lanes cover one row's 64 K-values

    float acc[2][8][4];
#pragma unroll
    for (int mi = 0; mi < 2; mi++)
#pragma unroll
        for (int nj = 0; nj < 8; nj++)
#pragma unroll
            for (int q = 0; q < 4; q++) acc[mi][nj][q] = 0.0f;

    uint2 xh[8];
    // ---- prologue: x chunk0 -> fp16 regs, B chunk0 via cp.async ----
#pragma unroll
    for (int p = 0; p < 8; p++) {
        int gr = r0 + (tid >> 4) + p * 16; if (gr >= n) gr = n - 1;
        xh[p] = cvt4h(*(const float4*)(x + (size_t)gr * 256 + iq * 4));
    }
    {
        const char* gB = (const char*)g_W1sw + (size_t)by * 16384;
#pragma unroll
        for (int i = 0; i < 4; i++) {
            int idx = tid + i * 256;
            cpa16(sb + 32768u + (uint32_t)idx * 16u, gB + (size_t)idx * 16);
        }
        CP_COMMIT();
    }

    // =================== mainloop: 4 K-chunks, fully double-buffered, 1 sync/chunk ===================
    for (int kt = 0; kt < 4; kt++) {
        const uint32_t aB = (uint32_t)(kt & 1) * 16384u;
        const uint32_t bB = 32768u + (uint32_t)(kt & 1) * 16384u;

        // store A chunk kt (safe: all warps passed previous sync => done reading this buffer)
#pragma unroll
        for (int p = 0; p < 8; p++) {
            int row = (tid >> 4) + p * 16;
            uint32_t o = aB + SW128((uint32_t)(row * 128 + iq * 8));
            *(uint2*)(sm + o) = xh[p];
        }
        // prefetch + convert next x chunk (hidden behind this chunk's compute)
        if (kt < 3) {
#pragma unroll
            for (int p = 0; p < 8; p++) {
                int gr = r0 + (tid >> 4) + p * 16; if (gr >= n) gr = n - 1;
                xh[p] = cvt4h(*(const float4*)(x + (size_t)gr * 256 + (kt + 1) * 64 + iq * 4));
            }
        }
        CP_WAIT0();            // B chunk kt arrived
        __syncthreads();       // A stores + B visible; prior chunk's readers done

        // issue next B chunk into the other buffer (lands during this chunk's compute)
        if (kt < 3) {
            const char* gB = (const char*)g_W1sw + (size_t)(kt + 1) * 32768 + (size_t)by * 16384;
            uint32_t dstB = 32768u + (uint32_t)((kt + 1) & 1) * 16384u;
#pragma unroll
            for (int i = 0; i < 4; i++) {
                int idx = tid + i * 256;
                cpa16(sb + dstB + (uint32_t)idx * 16u, gB + (size_t)idx * 16);
            }
            CP_COMMIT();
        }

        // ---- compute: 1-term (A·B) ----
#pragma unroll
        for (int kk = 0; kk < 4; kk++) {
            uint32_t af[2][4], bfr[8][2];
#pragma unroll
            for (int mi = 0; mi < 2; mi++) {
                int row = arow0 + mi * 16;
                uint32_t off = (uint32_t)(row * 128) + (((uint32_t)(kk * 32) + kba) ^ (uint32_t)((row & 7) << 4));
                LDSM4(af[mi][0], af[mi][1], af[mi][2], af[mi][3], sb + aB + off);
            }
#pragma unroll
            for (int g = 0; g < 4; g++) {
                int row = brow0 + g * 16;
                uint32_t off = (uint32_t)(row * 128) + (((uint32_t)(kk * 32) + kbb) ^ (uint32_t)((row & 7) << 4));
                LDSM4(bfr[2 * g][0], bfr[2 * g][1], bfr[2 * g + 1][0], bfr[2 * g + 1][1], sb + bB + off);
            }
#pragma unroll
            for (int mi = 0; mi < 2; mi++)
#pragma unroll
                for (int nj = 0; nj < 8; nj++) mma_f16(acc[mi][nj], af[mi], bfr[nj]);
        }
    }

    // ---- epilogue: act, single fp16, stage h1 half-image (ck = by) in B0 region ----
    // Stage [32768, 49152) is disjoint from kt=3's live buffers (A1 @16384, B1 @49152) => no sync first.
#pragma unroll
    for (int mi = 0; mi < 2; mi++)
#pragma unroll
        for (int nj = 0; nj < 8; nj++) {
            int rlo = wm * 32 + mi * 16 + (l >> 2);
            int j = by * 64 + wn * 32 + nj * 4 + (l & 3);       // global h1 column
            float v0 = gate_act(acc[mi][nj][0] + __ldg(bz + j), acc[mi][nj][1] + __ldg(bh + j));
            float v1 = gate_act(acc[mi][nj][2] + __ldg(bz + j), acc[mi][nj][3] + __ldg(bh + j));
            int kk2 = j & 63;
            uint32_t o0 = 32768u + SW128((uint32_t)(rlo * 128 + kk2 * 2));
            uint32_t o1 = 32768u + SW128((uint32_t)((rlo + 8) * 128 + kk2 * 2));
            *(__half*)(sm + o0) = __float2half_rn(v0);
            *(__half*)(sm + o1) = __float2half_rn(v1);
        }
    __syncthreads();
    {   // stage (16KB) -> g_h1img tile section ck=by, coalesced
        const uint4* s4 = (const uint4*)(sm + 32768);
        uint4* d4 = (uint4*)(g_h1img + (size_t)blockIdx.x * 32768 + (size_t)by * 16384);
#pragma unroll
        for (int i = 0; i < 4; i++) d4[tid + i * 256] = s4[tid + i * 256];
    }
}

// =================== layer 2 + lin1 + lin2: BM=128, BN=128, K=128 (2 chunks), fp16 1-term ===================
// SMEM: [0] A0 16K [16384] A1 16K [32768] B0 16K [49152] B1 16K
//       [65536] w3s 4K [69632] b3s 64B [69696] w4s 64B [69760] bzs 256B [70016] bhs 256B  total 70272
// h2s (128*65*4 = 33280B) overlaps [0, 33280) after the mainloop.
#define SM2_BYTES 70272

__global__ void __launch_bounds__(256, 2)
layer2_mma(const float* __restrict__ bz, const float* __restrict__ bh,
           const float* __restrict__ w3, const float* __restrict__ b3,
           const float* __restrict__ w4, const float* __restrict__ b4,
           float* __restrict__ out, int n) {
    extern __shared__ __align__(128) char sm[];
    const uint32_t sb = s2u(sm);
    const int tid = threadIdx.x, l = tid & 31, w = tid >> 5;
    const int wm = w >> 1, wn = w & 1;          // 4x2 warp grid, warp tile 32x64
    float* w3s = (float*)(sm + 65536);
    float* b3s = (float*)(sm + 69632);
    float* w4s = (float*)(sm + 69696);
    float* bzs = (float*)(sm + 69760);
    float* bhs = (float*)(sm + 70016);
#pragma unroll
    for (int i = 0; i < 4; i++) w3s[tid + i * 256] = w3[tid + i * 256];
    if (tid < 16) { b3s[tid] = b3[tid]; w4s[tid] = w4[tid]; }
    if (tid < 64) { bzs[tid] = bz[tid]; bhs[tid] = bh[tid]; }

    float acc[2][8][4];
#pragma unroll
    for (int mi = 0; mi < 2; mi++)
#pragma unroll
        for (int nj = 0; nj < 8; nj++)
#pragma unroll
            for (int q = 0; q < 4; q++) acc[mi][nj][q] = 0.0f;

    const int arow0 = wm * 32 + (l & 15);
    const uint32_t kba = (uint32_t)(((l >> 4) & 1) * 16);
    const int brow0 = wn * 64 + 8 * ((l >> 4) & 1) + (l & 7);
    const uint32_t kbb = (uint32_t)(((l >> 3) & 1) * 16);

    const int r0 = blockIdx.x * 128;

    // ---- prologue: A0 (16K) + B0 (16K) via cp.async ----
    {
        const char* gA = (const char*)g_h1img + (size_t)blockIdx.x * 32768;
        const char* gB = (const char*)g_W2sw;
#pragma unroll
        for (int i = 0; i < 4; i++) {
            int idx = tid + i * 256;
            cpa16(sb + (uint32_t)idx * 16u, gA + (size_t)idx * 16);
            cpa16(sb + 32768u + (uint32_t)idx * 16u, gB + (size_t)idx * 16);
        }
        CP_COMMIT();
    }

    for (int kt = 0; kt < 2; kt++) {
        const uint32_t aB = (uint32_t)kt * 16384u;
        const uint32_t bB = 32768u + (uint32_t)kt * 16384u;

        CP_WAIT0();
        __syncthreads();

        if (kt == 0) {   // prefetch chunk 1 during chunk 0 compute
            const char* gA = (const char*)g_h1img + (size_t)blockIdx.x * 32768 + 16384;
            const char* gB = (const char*)g_W2sw + 16384;
#pragma unroll
            for (int i = 0; i < 4; i++) {
                int idx = tid + i * 256;
                cpa16(sb + 16384u + (uint32_t)idx * 16u, gA + (size_t)idx * 16);
                cpa16(sb + 49152u + (uint32_t)idx * 16u, gB + (size_t)idx * 16);
            }
            CP_COMMIT();
        }

        // ---- compute: 1-term (A·B) ----
#pragma unroll
        for (int kk = 0; kk < 4; kk++) {
            uint32_t af[2][4], bfr[8][2];
#pragma unroll
            for (int mi = 0; mi < 2; mi++) {
                int row = arow0 + mi * 16;
                uint32_t off = (uint32_t)(row * 128) + (((uint32_t)(kk * 32) + kba) ^ (uint32_t)((row & 7) << 4));
                LDSM4(af[mi][0], af[mi][1], af[mi][2], af[mi][3], sb + aB + off);
            }
#pragma unroll
            for (int g = 0; g < 4; g++) {
                int row = brow0 + g * 16;
                uint32_t off = (uint32_t)(row * 128) + (((uint32_t)(kk * 32) + kbb) ^ (uint32_t)((row & 7) << 4));
                LDSM4(bfr[2 * g][0], bfr[2 * g][1], bfr[2 * g + 1][0], bfr[2 * g + 1][1], sb + bB + off);
            }
#pragma unroll
            for (int mi = 0; mi < 2; mi++)
#pragma unroll
                for (int nj = 0; nj < 8; nj++) mma_f16(acc[mi][nj], af[mi], bfr[nj]);
        }
    }
    __syncthreads();   // all compute done before h2s overwrites A/B regions

    // ---- epilogue: h2 -> smem ----
    float* h2s = (float*)sm;    // [128][65]
#pragma unroll
    for (int mi = 0; mi < 2; mi++)
#pragma unroll
        for (int nj = 0; nj < 8; nj++) {
            int rlo = wm * 32 + mi * 16 + (l >> 2);
            int j = wn * 32 + nj * 4 + (l & 3);
            float v0 = gate_act(acc[mi][nj][0] + bzs[j], acc[mi][nj][1] + bhs[j]);
            float v1 = gate_act(acc[mi][nj][2] + bzs[j], acc[mi][nj][3] + bhs[j]);
            h2s[rlo * 65 + j] = v0;
            h2s[(rlo + 8) * 65 + j] = v1;
        }
    __syncthreads();

    // ---- lin1(relu) + lin2: one thread per row ----
    if (tid < 128) {
        float s[16];
#pragma unroll
        for (int u = 0; u < 16; u++) s[u] = b3s[u];
#pragma unroll 4
        for (int j = 0; j < 64; j++) {
            float v = h2s[tid * 65 + j];
#pragma unroll
            for (int u = 0; u < 16; u++) s[u] = fmaf(v, w3s[j * 16 + u], s[u]);
        }
        float o2 = __ldg(b4);
#pragma unroll
        for (int u = 0; u < 16; u++) o2 += fmaxf(s[u], 0.0f) * w4s[u];
        int gr = r0 + tid;
        if (gr < n) out[gr] = o2;
    }
}

extern "C" void kernel_launch(void* const* d_in, const int* in_sizes, int n_in,
                              void* d_out, int out_size) {
    const float* x   = (const float*)d_in[0];
    const float* wz1 = (const float*)d_in[3];
    const float* bz1 = (const float*)d_in[4];
    const float* wh1 = (const float*)d_in[7];
    const float* bh1 = (const float*)d_in[8];
    const float* wz2 = (const float*)d_in[9];
    const float* bz2 = (const float*)d_in[10];
    const float* wh2 = (const float*)d_in[13];
    const float* bh2 = (const float*)d_in[14];
    const float* w3  = (const float*)d_in[15];
    const float* b3  = (const float*)d_in[16];
    const float* w4  = (const float*)d_in[17];
    const float* b4  = (const float*)d_in[18];

    const int n  = in_sizes[0] / 256;          // 100000
    const int nb = (n + 127) / 128;            // 782

    cudaFuncSetAttribute(layer1_mma, cudaFuncAttributeMaxDynamicSharedMemorySize, SM1_BYTES);
    cudaFuncSetAttribute(layer2_mma, cudaFuncAttributeMaxDynamicSharedMemorySize, SM2_BYTES);

    prep_kernel<<<256, 256>>>(wz1, wh1, wz2, wh2);
    layer1_mma<<<dim3(nb, 2), 256, SM1_BYTES>>>(x, bz1, bh1, n);
    layer2_mma<<<nb, 256, SM2_BYTES>>>(bz2, bh2, w3, b3, w4, b4, (float*)d_out, n);
}

// round 15
// speedup vs baseline: 1.3879x; 1.0348x over previous
#include <cuda_runtime.h>
#include <cuda_fp16.h>
#include <cstdint>

#define NB_MAX 782            // ceil(100000/128)

// ---------------- device scratch (no allocs allowed) ----------------
// W1 pre-swizzled fp16 (single term): [kt=4][N=256 rows][128B] = 32KB per kt
__device__ __align__(16) unsigned char g_W1sw[4 * 32768];
// W2 pre-swizzled fp16 (single term): [kt=2][16KB]
__device__ __align__(16) unsigned char g_W2sw[2 * 16384];
// h1 per-tile A images (single fp16): [ck=2][16KB] = 32KB per 128-row tile
__device__ __align__(16) unsigned char g_h1img[(size_t)NB_MAX * 32768];
// per-tile completion flags (0..2), zeroed by prep each launch
__device__ int g_done[NB_MAX];

// ---------------- helpers ----------------
__device__ __forceinline__ uint32_t s2u(const void* p) {
    uint32_t a;
    asm("{ .reg .u64 t; cvta.to.shared.u64 t, %1; cvt.u32.u64 %0, t; }" : "=r"(a) : "l"(p));
    return a;
}
#define SW128(o) ((o) ^ (((o) >> 3) & 0x70))

#define LDSM4(R0, R1, R2, R3, A) \
    asm volatile("ldmatrix.sync.aligned.m8n8.x4.shared.b16 {%0,%1,%2,%3}, [%4];" \
                 : "=r"(R0), "=r"(R1), "=r"(R2), "=r"(R3) : "r"(A))

__device__ __forceinline__ void mma_f16(float d[4], const uint32_t a[4], const uint32_t b[2]) {
    asm volatile(
        "mma.sync.aligned.m16n8k16.row.col.f32.f16.f16.f32 "
        "{%0,%1,%2,%3}, {%4,%5,%6,%7}, {%8,%9}, {%0,%1,%2,%3};"
        : "+f"(d[0]), "+f"(d[1]), "+f"(d[2]), "+f"(d[3])
        : "r"(a[0]), "r"(a[1]), "r"(a[2]), "r"(a[3]), "r"(b[0]), "r"(b[1]));
}

__device__ __forceinline__ void cpa16(uint32_t saddr, const void* g) {
    asm volatile("cp.async.cg.shared.global [%0], [%1], 16;" :: "r"(saddr), "l"(g));
}
#define CP_COMMIT() asm volatile("cp.async.commit_group;" ::: "memory")
#define CP_WAIT0()  asm volatile("cp.async.wait_group 0;" ::: "memory")

__device__ __forceinline__ uint2 cvt4h(float4 v) {
    __half2 p0 = __floats2half2_rn(v.x, v.y);
    __half2 p1 = __floats2half2_rn(v.z, v.w);
    uint2 r;
    r.x = *reinterpret_cast<uint32_t*>(&p0);
    r.y = *reinterpret_cast<uint32_t*>(&p1);
    return r;
}

// h = relu( sigmoid(-uz) * tanh(uh) )   [GRU cell with h0 = 0]
__device__ __forceinline__ float gate_act(float uz, float uh) {
    float s = 1.0f / (1.0f + __expf(uz));
    float t = tanhf(uh);
    return fmaxf(s * t, 0.0f);
}

// ---------------- prep: combine W[0,0]+W[1,0], interleave z/h cols, single fp16, swizzle ----------------
__global__ void prep_kernel(const float* __restrict__ wz1, const float* __restrict__ wh1,
                            const float* __restrict__ wz2, const float* __restrict__ wh2) {
    int i = blockIdx.x * blockDim.x + threadIdx.x;   // 65536 threads
    if (i < NB_MAX) g_done[i] = 0;                   // reset flags every launch
    {   // W1: B operand [n=256][k=256]; n=2j -> z_j, n=2j+1 -> h_j
        int nn = i >> 8, k = i & 255;
        int j = nn >> 1;
        const float* src = (nn & 1) ? wh1 : wz1;
        float w = src[k * 128 + j] + src[49152 + k * 128 + j];
        int kt = k >> 6, kk = k & 63;
        uint32_t o = (uint32_t)(kt * 32768) + SW128((uint32_t)(nn * 128 + kk * 2));
        *(__half*)(g_W1sw + o) = __float2half_rn(w);
    }
    if (i < 16384) {   // W2: [n=128][k=128], single fp16
        int nn = i >> 7, k = i & 127;
        int j = nn >> 1;
        const float* src = (nn & 1) ? wh2 : wz2;
        float w = src[k * 64 + j] + src[12288 + k * 64 + j];
        int kt = k >> 6, kk = k & 63;
        uint32_t o = (uint32_t)(kt * 16384) + SW128((uint32_t)(nn * 128 + kk * 2));
        *(__half*)(g_W2sw + o) = __float2half_rn(w);
    }
}

// =================== persistent fused kernel ===================
// Unit list: u in [0, 2*nb)  -> layer1 half-tile (bx = u>>1, by = u&1)
//            u in [2*nb, 3*nb) -> layer2 tile (bx = u - 2*nb), waits on g_done[bx]==2
// SMEM (70272B), occ 2:
//   layer1 path: [0] A0 16K [16384] A1 16K [32768] B0 16K [49152] B1 16K; h1 stage in B0
//   layer2 path: [0] A0 [16384] A1 [32768] B0 [49152] B1
//   shared tail (loaded once at kernel entry, untouched by layer1 path):
//   [65536] w3s 4K [69632] b3s 64B [69696] w4s 64B [69760] bz2s 256B [70016] bh2s 256B
#define SM_BYTES 70272

__global__ void __launch_bounds__(256, 2)
fused_persist(const float* __restrict__ x,
              const float* __restrict__ bz1, const float* __restrict__ bh1,
              const float* __restrict__ bz2, const float* __restrict__ bh2,
              const float* __restrict__ w3, const float* __restrict__ b3,
              const float* __restrict__ w4, const float* __restrict__ b4,
              float* __restrict__ out, int n, int nb) {
    extern __shared__ __align__(128) char sm[];
    const uint32_t sb = s2u(sm);
    const int tid = threadIdx.x, l = tid & 31, w = tid >> 5;
    const int wm = w >> 1, wn = w & 1;          // 4x2 warp grid, warp tile 32x64

    float* w3s  = (float*)(sm + 65536);
    float* b3s  = (float*)(sm + 69632);
    float* w4s  = (float*)(sm + 69696);
    float* bz2s = (float*)(sm + 69760);
    float* bh2s = (float*)(sm + 70016);
#pragma unroll
    for (int i = 0; i < 4; i++) w3s[tid + i * 256] = w3[tid + i * 256];
    if (tid < 16) { b3s[tid] = b3[tid]; w4s[tid] = w4[tid]; }
    if (tid < 64) { bz2s[tid] = bz2[tid]; bh2s[tid] = bh2[tid]; }
    __syncthreads();

    // lane geometry (shared by both paths)
    const int arow0 = wm * 32 + (l & 15);
    const uint32_t kba = (uint32_t)(((l >> 4) & 1) * 16);
    const int brow0 = wn * 64 + 8 * ((l >> 4) & 1) + (l & 7);
    const uint32_t kbb = (uint32_t)(((l >> 3) & 1) * 16);
    const int iq = tid & 15;

    const int NL1 = nb * 2;
    const int NTOT = nb * 3;

    for (int u = blockIdx.x; u < NTOT; u += gridDim.x) {
        if (u < NL1) {
            // ================= layer1 half-tile =================
            const int bx = u >> 1, by = u & 1;
            const int r0 = bx * 128;

            float acc[2][8][4];
#pragma unroll
            for (int mi = 0; mi < 2; mi++)
#pragma unroll
                for (int nj = 0; nj < 8; nj++)
#pragma unroll
                    for (int q = 0; q < 4; q++) acc[mi][nj][q] = 0.0f;

            uint2 xh[8];
#pragma unroll
            for (int p = 0; p < 8; p++) {
                int gr = r0 + (tid >> 4) + p * 16; if (gr >= n) gr = n - 1;
                xh[p] = cvt4h(*(const float4*)(x + (size_t)gr * 256 + iq * 4));
            }
            {
                const char* gB = (const char*)g_W1sw + (size_t)by * 16384;
#pragma unroll
                for (int i = 0; i < 4; i++) {
                    int idx = tid + i * 256;
                    cpa16(sb + 32768u + (uint32_t)idx * 16u, gB + (size_t)idx * 16);
                }
                CP_COMMIT();
            }

            for (int kt = 0; kt < 4; kt++) {
                const uint32_t aB = (uint32_t)(kt & 1) * 16384u;
                const uint32_t bB = 32768u + (uint32_t)(kt & 1) * 16384u;

#pragma unroll
                for (int p = 0; p < 8; p++) {
                    int row = (tid >> 4) + p * 16;
                    uint32_t o = aB + SW128((uint32_t)(row * 128 + iq * 8));
                    *(uint2*)(sm + o) = xh[p];
                }
                if (kt < 3) {
#pragma unroll
                    for (int p = 0; p < 8; p++) {
                        int gr = r0 + (tid >> 4) + p * 16; if (gr >= n) gr = n - 1;
                        xh[p] = cvt4h(*(const float4*)(x + (size_t)gr * 256 + (kt + 1) * 64 + iq * 4));
                    }
                }
                CP_WAIT0();
                __syncthreads();

                if (kt < 3) {
                    const char* gB = (const char*)g_W1sw + (size_t)(kt + 1) * 32768 + (size_t)by * 16384;
                    uint32_t dstB = 32768u + (uint32_t)((kt + 1) & 1) * 16384u;
#pragma unroll
                    for (int i = 0; i < 4; i++) {
                        int idx = tid + i * 256;
                        cpa16(sb + dstB + (uint32_t)idx * 16u, gB + (size_t)idx * 16);
                    }
                    CP_COMMIT();
                }

#pragma unroll
                for (int kk = 0; kk < 4; kk++) {
                    uint32_t af[2][4], bfr[8][2];
#pragma unroll
                    for (int mi = 0; mi < 2; mi++) {
                        int row = arow0 + mi * 16;
                        uint32_t off = (uint32_t)(row * 128) + (((uint32_t)(kk * 32) + kba) ^ (uint32_t)((row & 7) << 4));
                        LDSM4(af[mi][0], af[mi][1], af[mi][2], af[mi][3], sb + aB + off);
                    }
#pragma unroll
                    for (int g = 0; g < 4; g++) {
                        int row = brow0 + g * 16;
                        uint32_t off = (uint32_t)(row * 128) + (((uint32_t)(kk * 32) + kbb) ^ (uint32_t)((row & 7) << 4));
                        LDSM4(bfr[2 * g][0], bfr[2 * g][1], bfr[2 * g + 1][0], bfr[2 * g + 1][1], sb + bB + off);
                    }
#pragma unroll
                    for (int mi = 0; mi < 2; mi++)
#pragma unroll
                        for (int nj = 0; nj < 8; nj++) mma_f16(acc[mi][nj], af[mi], bfr[nj]);
                }
            }

            // epilogue: act -> fp16, stage half-image in B0 (free: kt=3 used A1/B1)
#pragma unroll
            for (int mi = 0; mi < 2; mi++)
#pragma unroll
                for (int nj = 0; nj < 8; nj++) {
                    int rlo = wm * 32 + mi * 16 + (l >> 2);
                    int j = by * 64 + wn * 32 + nj * 4 + (l & 3);
                    float v0 = gate_act(acc[mi][nj][0] + __ldg(bz1 + j), acc[mi][nj][1] + __ldg(bh1 + j));
                    float v1 = gate_act(acc[mi][nj][2] + __ldg(bz1 + j), acc[mi][nj][3] + __ldg(bh1 + j));
                    int kk2 = j & 63;
                    uint32_t o0 = 32768u + SW128((uint32_t)(rlo * 128 + kk2 * 2));
                    uint32_t o1 = 32768u + SW128((uint32_t)((rlo + 8) * 128 + kk2 * 2));
                    *(__half*)(sm + o0) = __float2half_rn(v0);
                    *(__half*)(sm + o1) = __float2half_rn(v1);
                }
            __syncthreads();
            {   // stage (16KB) -> g_h1img section ck=by
                const uint4* s4 = (const uint4*)(sm + 32768);
                uint4* d4 = (uint4*)(g_h1img + (size_t)bx * 32768 + (size_t)by * 16384);
#pragma unroll
                for (int i = 0; i < 4; i++) d4[tid + i * 256] = s4[tid + i * 256];
            }
            // publish: all writes -> fence -> barrier -> single arrival
            __threadfence();
            __syncthreads();
            if (tid == 0) atomicAdd(&g_done[bx], 1);
            // (next unit's smem writes are safe: barrier above drained stage reads)
        } else {
            // ================= layer2 + lin1 + lin2 tile =================
            const int bx = u - NL1;
            const int r0 = bx * 128;

            if (tid == 0) {
                while (atomicAdd(&g_done[bx], 0) < 2) __nanosleep(64);
            }
            __syncthreads();   // acquire: flag seen -> h1img (L2-resident) readable

            float acc[2][8][4];
#pragma unroll
            for (int mi = 0; mi < 2; mi++)
#pragma unroll
                for (int nj = 0; nj < 8; nj++)
#pragma unroll
                    for (int q = 0; q < 4; q++) acc[mi][nj][q] = 0.0f;

            {   // prologue: A0 + B0
                const char* gA = (const char*)g_h1img + (size_t)bx * 32768;
                const char* gB = (const char*)g_W2sw;
#pragma unroll
                for (int i = 0; i < 4; i++) {
                    int idx = tid + i * 256;
                    cpa16(sb + (uint32_t)idx * 16u, gA + (size_t)idx * 16);
                    cpa16(sb + 32768u + (uint32_t)idx * 16u, gB + (size_t)idx * 16);
                }
                CP_COMMIT();
            }

            for (int kt = 0; kt < 2; kt++) {
                const uint32_t aB = (uint32_t)kt * 16384u;
                const uint32_t bB = 32768u + (uint32_t)kt * 16384u;

                CP_WAIT0();
                __syncthreads();

                if (kt == 0) {
                    const char* gA = (const char*)g_h1img + (size_t)bx * 32768 + 16384;
                    const char* gB = (const char*)g_W2sw + 16384;
#pragma unroll
                    for (int i = 0; i < 4; i++) {
                        int idx = tid + i * 256;
                        cpa16(sb + 16384u + (uint32_t)idx * 16u, gA + (size_t)idx * 16);
                        cpa16(sb + 49152u + (uint32_t)idx * 16u, gB + (size_t)idx * 16);
                    }
                    CP_COMMIT();
                }

#pragma unroll
                for (int kk = 0; kk < 4; kk++) {
                    uint32_t af[2][4], bfr[8][2];
#pragma unroll
                    for (int mi = 0; mi < 2; mi++) {
                        int row = arow0 + mi * 16;
                        uint32_t off = (uint32_t)(row * 128) + (((uint32_t)(kk * 32) + kba) ^ (uint32_t)((row & 7) << 4));
                        LDSM4(af[mi][0], af[mi][1], af[mi][2], af[mi][3], sb + aB + off);
                    }
#pragma unroll
                    for (int g = 0; g < 4; g++) {
                        int row = brow0 + g * 16;
                        uint32_t off = (uint32_t)(row * 128) + (((uint32_t)(kk * 32) + kbb) ^ (uint32_t)((row & 7) << 4));
                        LDSM4(bfr[2 * g][0], bfr[2 * g][1], bfr[2 * g + 1][0], bfr[2 * g + 1][1], sb + bB + off);
                    }
#pragma unroll
                    for (int mi = 0; mi < 2; mi++)
#pragma unroll
                        for (int nj = 0; nj < 8; nj++) mma_f16(acc[mi][nj], af[mi], bfr[nj]);
                }
            }
            __syncthreads();   // compute done before h2s overwrites A/B regions

            float* h2s = (float*)sm;    // [128][65]
#pragma unroll
            for (int mi = 0; mi < 2; mi++)
#pragma unroll
                for (int nj = 0; nj < 8; nj++) {
                    int rlo = wm * 32 + mi * 16 + (l >> 2);
                    int j = wn * 32 + nj * 4 + (l & 3);
                    float v0 = gate_act(acc[mi][nj][0] + bz2s[j], acc[mi][nj][1] + bh2s[j]);
                    float v1 = gate_act(acc[mi][nj][2] + bz2s[j], acc[mi][nj][3] + bh2s[j]);
                    h2s[rlo * 65 + j] = v0;
                    h2s[(rlo + 8) * 65 + j] = v1;
                }
            __syncthreads();

            if (tid < 128) {
                float s[16];
#pragma unroll
                for (int uu = 0; uu < 16; uu++) s[uu] = b3s[uu];
#pragma unroll 4
                for (int j = 0; j < 64; j++) {
                    float v = h2s[tid * 65 + j];
#pragma unroll
                    for (int uu = 0; uu < 16; uu++) s[uu] = fmaf(v, w3s[j * 16 + uu], s[uu]);
                }
                float o2 = __ldg(b4);
#pragma unroll
                for (int uu = 0; uu < 16; uu++) o2 += fmaxf(s[uu], 0.0f) * w4s[uu];
                int gr = r0 + tid;
                if (gr < n) out[gr] = o2;
            }
            __syncthreads();   // h2s reads done before next unit reuses smem
        }
    }
}

extern "C" void kernel_launch(void* const* d_in, const int* in_sizes, int n_in,
                              void* d_out, int out_size) {
    const float* x   = (const float*)d_in[0];
    const float* wz1 = (const float*)d_in[3];
    const float* bz1 = (const float*)d_in[4];
    const float* wh1 = (const float*)d_in[7];
    const float* bh1 = (const float*)d_in[8];
    const float* wz2 = (const float*)d_in[9];
    const float* bz2 = (const float*)d_in[10];
    const float* wh2 = (const float*)d_in[13];
    const float* bh2 = (const float*)d_in[14];
    const float* w3  = (const float*)d_in[15];
    const float* b3  = (const float*)d_in[16];
    const float* w4  = (const float*)d_in[17];
    const float* b4  = (const float*)d_in[18];

    const int n  = in_sizes[0] / 256;          // 100000
    const int nb = (n + 127) / 128;            // 782

    int dev = 0, nsm = 148;
    cudaGetDevice(&dev);
    cudaDeviceGetAttribute(&nsm, cudaDevAttrMultiProcessorCount, dev);
    int grid = nsm * 2;                        // exactly resident at occupancy 2
    if (grid > nb * 3) grid = nb * 3;

    cudaFuncSetAttribute(fused_persist, cudaFuncAttributeMaxDynamicSharedMemorySize, SM_BYTES);

    prep_kernel<<<256, 256>>>(wz1, wh1, wz2, wh2);
    fused_persist<<<grid, 256, SM_BYTES>>>(x, bz1, bh1, bz2, bh2, w3, b3, w4, b4,
                                           (float*)d_out, n, nb);
}